// round 3
// baseline (speedup 1.0000x reference)
#include <cuda_runtime.h>
#include <cstdint>

#define BATCH 8
#define NPTS  4096
#define CH    128
#define KNN   16
#define NDS   2048

// scratch (allocation-free rule: device globals)
__device__ float g_scores[BATCH * NPTS];
__device__ int   g_idx[BATCH * NDS];

// XLA:GPU small-row reduction order for a 16-element row:
// lane l holds v[l]; shfl_down offsets 8,4,2,1 =>
// (((v0+v8)+(v4+v12))+((v2+v10)+(v6+v14))) + (((v1+v9)+(v5+v13))+((v3+v11)+(v7+v15)))
__device__ __forceinline__ float tree16(const float* v) {
    float s8[8], s4[4], s2[2];
    #pragma unroll
    for (int l = 0; l < 8; ++l) s8[l] = __fadd_rn(v[l], v[l + 8]);
    #pragma unroll
    for (int l = 0; l < 4; ++l) s4[l] = __fadd_rn(s8[l], s8[l + 4]);
    #pragma unroll
    for (int l = 0; l < 2; ++l) s2[l] = __fadd_rn(s4[l], s4[l + 2]);
    return __fadd_rn(s2[0], s2[1]);
}

// ---------------------------------------------------------------------------
// Kernel 1: per-point KNN score.
// One thread per query point. All 4096 candidate coords (+precomputed sq) of
// the batch live in shared as float4. Top-16 smallest (d2,idx) keys kept in a
// per-thread max-heap in shared memory, guarded by a cached 32-bit threshold.
// Score recomputed from coordinate diffs matching the reference reduce order:
// reduce over k first (tree16, XLA row-reduce), then sequential over d.
// ---------------------------------------------------------------------------
__global__ void __launch_bounds__(128, 2) knn_score_kernel(const float* __restrict__ x) {
    extern __shared__ unsigned char smem[];
    float4* pts = (float4*)smem;                                        // 4096*16 = 64KB
    unsigned long long* heap = (unsigned long long*)(smem + NPTS * 16); // 16*128*8 = 16KB

    const int b   = blockIdx.y;
    const int tid = threadIdx.x;
    const float* xb = x + b * 3 * NPTS;

    for (int m = tid; m < NPTS; m += 128) {
        float v0 = xb[m], v1 = xb[NPTS + m], v2 = xb[2 * NPTS + m];
        float sq = __fadd_rn(__fadd_rn(__fmul_rn(v0, v0), __fmul_rn(v1, v1)),
                             __fmul_rn(v2, v2));
        pts[m] = make_float4(v0, v1, v2, sq);
    }
#define H(j) heap[(j) * 128 + tid]
    #pragma unroll
    for (int k = 0; k < KNN; ++k) H(k) = 0xFFFFFFFFFFFFFFFFull;
    __syncthreads();

    const int q = blockIdx.x * 128 + tid;
    const float4 me = pts[q];
    unsigned int thrHi = 0xFFFFFFFFu;

    #pragma unroll 4
    for (int m = 0; m < NPTS; ++m) {
        float4 p = pts[m];  // broadcast LDS.128
        float inner = fmaf(me.z, p.z, fmaf(me.y, p.y, __fmul_rn(me.x, p.x)));
        float d2 = __fsub_rn(__fadd_rn(me.w, p.w), __fmul_rn(2.0f, inner));
        unsigned int ub = __float_as_uint(d2);
        ub ^= ((unsigned int)(((int)ub) >> 31)) | 0x80000000u;  // order-preserving map
        // Equal hi-bits: new index m > all stored indices -> ranks after -> skip.
        if (ub < thrHi) {
            unsigned long long key = ((unsigned long long)ub << 32) | (unsigned int)m;
            int i = 0;
            #pragma unroll
            for (int lvl = 0; lvl < 4; ++lvl) {
                int l = 2 * i + 1;
                if (l >= KNN) break;
                int r = l + 1;
                unsigned long long cb = H(l);
                int bi = l;
                if (r < KNN) {
                    unsigned long long cr = H(r);
                    if (cr > cb) { cb = cr; bi = r; }
                }
                if (cb > key) { H(i) = cb; i = bi; } else break;
            }
            H(i) = key;
            thrHi = (unsigned int)(H(0) >> 32);
        }
    }

    // extract + sort the 16 keys ascending (static register indices after unroll)
    unsigned long long arr[KNN];
    #pragma unroll
    for (int k = 0; k < KNN; ++k) arr[k] = H(k);
    #pragma unroll
    for (int i = 0; i < KNN - 1; ++i) {
        #pragma unroll
        for (int j = 0; j < KNN - 1 - i; ++j) {
            unsigned long long a0 = arr[j], a1 = arr[j + 1];
            bool sw = a0 > a1;
            arr[j]     = sw ? a1 : a0;
            arr[j + 1] = sw ? a0 : a1;
        }
    }
#undef H

    float4 nb[KNN];
    #pragma unroll
    for (int k = 0; k < KNN; ++k) nb[k] = pts[(unsigned int)arr[k]];

    // score: reduce k first (tree16 per coordinate d), then sequentially over d
    float vx[KNN], vy[KNN], vz[KNN];
    #pragma unroll
    for (int k = 0; k < KNN; ++k) {
        float tx = __fsub_rn(nb[k].x, me.x);
        float ty = __fsub_rn(nb[k].y, me.y);
        float tz = __fsub_rn(nb[k].z, me.z);
        vx[k] = __fmul_rn(tx, tx);
        vy[k] = __fmul_rn(ty, ty);
        vz[k] = __fmul_rn(tz, tz);
    }
    float T0 = tree16(vx);
    float T1 = tree16(vy);
    float T2 = tree16(vz);
    float score = __fadd_rn(__fadd_rn(T0, T1), T2);

    g_scores[b * NPTS + q] = score;
}

// ---------------------------------------------------------------------------
// Kernel 2: per-batch full bitonic sort of 4096 keys (descending score,
// ascending index on ties), emit first NDS indices in rank order.
// key = (~mapped(score) << 32) | idx  -> ascending u64 sort gives the order.
// ---------------------------------------------------------------------------
__global__ void __launch_bounds__(1024) sort_kernel() {
    __shared__ unsigned long long sh[NPTS];
    const int b = blockIdx.x, tid = threadIdx.x;

    for (int i = tid; i < NPTS; i += 1024) {
        unsigned int ub = __float_as_uint(g_scores[b * NPTS + i]);
        ub ^= ((unsigned int)(((int)ub) >> 31)) | 0x80000000u;
        sh[i] = (((unsigned long long)(~ub)) << 32) | (unsigned int)i;
    }
    __syncthreads();

    for (int k = 2; k <= NPTS; k <<= 1) {
        for (int j = k >> 1; j > 0; j >>= 1) {
            for (int t = tid; t < NPTS; t += 1024) {
                int ixj = t ^ j;
                if (ixj > t) {
                    unsigned long long A = sh[t], Bv = sh[ixj];
                    bool up = ((t & k) == 0);
                    if ((A > Bv) == up) { sh[t] = Bv; sh[ixj] = A; }
                }
            }
            __syncthreads();
        }
    }
    for (int j = tid; j < NDS; j += 1024)
        g_idx[b * NDS + j] = (int)(unsigned int)sh[j];
}

// ---------------------------------------------------------------------------
// Kernel 3: gather. out = [xyz (8*3*2048) | points (8*128*2048)]
// ---------------------------------------------------------------------------
__global__ void gather_kernel(const float* __restrict__ x,
                              const float* __restrict__ y,
                              float* __restrict__ out) {
    int t = blockIdx.x * blockDim.x + threadIdx.x;
    const int XYZ = BATCH * 3 * NDS;
    if (t < XYZ) {
        int j = t % NDS;
        int rest = t / NDS;
        int d = rest % 3;
        int b = rest / 3;
        int src = g_idx[b * NDS + j];
        out[t] = x[(b * 3 + d) * NPTS + src];
    } else {
        int t2 = t - XYZ;
        if (t2 < BATCH * CH * NDS) {
            int j = t2 % NDS;
            int rest = t2 / NDS;
            int c = rest % CH;
            int b = rest / CH;
            int src = g_idx[b * NDS + j];
            out[XYZ + t2] = y[(b * CH + c) * NPTS + src];
        }
    }
}

extern "C" void kernel_launch(void* const* d_in, const int* in_sizes, int n_in,
                              void* d_out, int out_size) {
    const float* x = (const float*)d_in[0];
    const float* y = (const float*)d_in[1];
    float* out = (float*)d_out;

    static const size_t kSmem = NPTS * 16 + KNN * 128 * 8;  // 81920 bytes
    cudaFuncSetAttribute(knn_score_kernel,
                         cudaFuncAttributeMaxDynamicSharedMemorySize, (int)kSmem);

    dim3 gridA(NPTS / 128, BATCH);
    knn_score_kernel<<<gridA, 128, kSmem>>>(x);
    sort_kernel<<<BATCH, 1024>>>();

    const int total = BATCH * 3 * NDS + BATCH * CH * NDS;
    gather_kernel<<<(total + 255) / 256, 256>>>(x, y, out);
}